// round 2
// baseline (speedup 1.0000x reference)
#include <cuda_runtime.h>
#include <cstdint>

typedef unsigned long long u64;

__device__ __forceinline__ u64 pack2(float lo, float hi) {
    u64 r;
    asm("mov.b64 %0, {%1, %2};" : "=l"(r) : "f"(lo), "f"(hi));
    return r;
}
__device__ __forceinline__ void unpack2(u64 v, float& lo, float& hi) {
    asm("mov.b64 {%0, %1}, %2;" : "=f"(lo), "=f"(hi) : "l"(v));
}
__device__ __forceinline__ u64 fma2(u64 a, u64 b, u64 c) {
    u64 d;
    asm("fma.rn.f32x2 %0, %1, %2, %3;" : "=l"(d) : "l"(a), "l"(b), "l"(c));
    return d;
}

// ---------------------------------------------------------------------------
// Fast path: S=4096, D=64, L=12. One thread per q. K_g/V_g broadcast from
// SMEM; Q loads and context stores staged through per-warp SMEM transpose
// buffers so the gmem side is coalesced. Mask is int32 (harness materializes
// jnp.bool_ as int32).
// ---------------------------------------------------------------------------
__global__ __launch_bounds__(128)
void logtrans_fast(const float4* __restrict__ Q4,
                   const float4* __restrict__ K4,
                   const float4* __restrict__ V4,
                   const int* __restrict__ M,
                   float4* __restrict__ C4,
                   float* __restrict__ A)
{
    constexpr int S = 4096;
    constexpr int L = 12;

    __shared__ float4 ks[L][16];
    __shared__ float4 vs[L][16];
    __shared__ float4 buf[4][32][5];   // per-warp staging, padded row (5 float4)

    const int tid  = threadIdx.x;
    const int lane = tid & 31;
    const int w    = tid >> 5;
    const int bh   = blockIdx.y;
    const int q0   = blockIdx.x * 128;

    const int IND[L] = {0, 2048, 3072, 3584, 3840, 3968, 4032, 4064,
                        4080, 4088, 4092, 4094};

    // Fill K_g / V_g tiles (12 x 64 floats each)
    for (int e = tid; e < L * 16; e += 128) {
        int j = e >> 4, c = e & 15;
        long long row = (long long)bh * S + IND[j];
        ks[j][c] = __ldg(&K4[row * 16 + c]);
        vs[j][c] = __ldg(&V4[row * 16 + c]);
    }

    // Mask row for this q: 10 scalar int loads + one int4 covering 4092/4094
    const long long qg = (long long)bh * S + q0 + tid;
    const int* mrow = M + qg * (long long)S;
    unsigned mw = 0;
    {
        const int SI[10] = {0, 2048, 3072, 3584, 3840, 3968, 4032, 4064,
                            4080, 4088};
#pragma unroll
        for (int j = 0; j < 10; ++j)
            mw |= (mrow[SI[j]] ? 1u : 0u) << j;
        int4 t = *reinterpret_cast<const int4*>(mrow + 4092); // 4092..4095
        mw |= (t.x ? 1u : 0u) << 10;   // 4092
        mw |= (t.z ? 1u : 0u) << 11;   // 4094
    }
    __syncthreads();

    // ---------------- scores: s[j] = Q . K_g[j] ----------------
    u64 s2[L];
#pragma unroll
    for (int j = 0; j < L; ++j) s2[j] = 0ull;

    const float4* Qb = Q4 + ((long long)bh * S + q0 + w * 32) * 16;

#pragma unroll
    for (int dc = 0; dc < 4; ++dc) {
        __syncwarp();
        // coalesced gmem -> staged SMEM (this warp's 32 rows, 16-float chunk)
#pragma unroll
        for (int it = 0; it < 4; ++it) {
            int idx = it * 32 + lane;
            buf[w][idx >> 2][idx & 3] =
                Qb[(long long)(idx >> 2) * 16 + dc * 4 + (idx & 3)];
        }
        __syncwarp();
        ulonglong2 qv[4];
#pragma unroll
        for (int c = 0; c < 4; ++c)
            qv[c] = *reinterpret_cast<const ulonglong2*>(&buf[w][lane][c]);

#pragma unroll
        for (int j = 0; j < L; ++j) {
#pragma unroll
            for (int c = 0; c < 4; ++c) {
                ulonglong2 kv =
                    *reinterpret_cast<const ulonglong2*>(&ks[j][dc * 4 + c]);
                s2[j] = fma2(qv[c].x, kv.x, s2[j]);
                s2[j] = fma2(qv[c].y, kv.y, s2[j]);
            }
        }
    }

    // ---------------- mask + softmax ----------------
    float sc[L];
#pragma unroll
    for (int j = 0; j < L; ++j) {
        float lo, hi;
        unpack2(s2[j], lo, hi);
        float v = (lo + hi) * 0.125f;               // / sqrt(64)
        sc[j] = ((mw >> j) & 1u) ? -1e9f : v;
    }
    float m = sc[0];
#pragma unroll
    for (int j = 1; j < L; ++j) m = fmaxf(m, sc[j]);
    float sum = 0.f;
#pragma unroll
    for (int j = 0; j < L; ++j) {
        float e = __expf(sc[j] - m);
        sc[j] = e;
        sum += e;
    }
    float inv = 1.0f / sum;
    u64 a2[L];
#pragma unroll
    for (int j = 0; j < L; ++j) {
        float a = sc[j] * inv;
        sc[j] = a;
        a2[j] = pack2(a, a);
    }

    // ---------------- context = attn @ V_g ----------------
    float4* Cb = C4 + ((long long)bh * S + q0 + w * 32) * 16;

#pragma unroll
    for (int dc = 0; dc < 4; ++dc) {
        ulonglong2 acc[4];
#pragma unroll
        for (int c = 0; c < 4; ++c) { acc[c].x = 0ull; acc[c].y = 0ull; }
#pragma unroll
        for (int j = 0; j < L; ++j) {
#pragma unroll
            for (int c = 0; c < 4; ++c) {
                ulonglong2 vv =
                    *reinterpret_cast<const ulonglong2*>(&vs[j][dc * 4 + c]);
                acc[c].x = fma2(a2[j], vv.x, acc[c].x);
                acc[c].y = fma2(a2[j], vv.y, acc[c].y);
            }
        }
        __syncwarp();   // prior buf readers done
#pragma unroll
        for (int c = 0; c < 4; ++c)
            *reinterpret_cast<ulonglong2*>(&buf[w][lane][c]) = acc[c];
        __syncwarp();
        // staged SMEM -> coalesced gmem
#pragma unroll
        for (int it = 0; it < 4; ++it) {
            int idx = it * 32 + lane;
            Cb[(long long)(idx >> 2) * 16 + dc * 4 + (idx & 3)] =
                buf[w][idx >> 2][idx & 3];
        }
    }

    // ---------------- attn output (12 floats per q, 16B-aligned) ----------
    float* ap = A + qg * 12;
    float4 o0 = make_float4(sc[0], sc[1], sc[2],  sc[3]);
    float4 o1 = make_float4(sc[4], sc[5], sc[6],  sc[7]);
    float4 o2 = make_float4(sc[8], sc[9], sc[10], sc[11]);
    *reinterpret_cast<float4*>(ap)     = o0;
    *reinterpret_cast<float4*>(ap + 4) = o1;
    *reinterpret_cast<float4*>(ap + 8) = o2;
}

// ---------------------------------------------------------------------------
// Generic fallback (any power-of-two S, D=64)
// ---------------------------------------------------------------------------
__global__ void logtrans_generic(const float* __restrict__ Q,
                                 const float* __restrict__ K,
                                 const float* __restrict__ V,
                                 const int* __restrict__ M,
                                 float* __restrict__ C,
                                 float* __restrict__ A,
                                 int S, int L, long long BHS)
{
    long long qg = (long long)blockIdx.x * blockDim.x + threadIdx.x;
    if (qg >= BHS) return;
    int bh = (int)(qg / S);
    const float* qr = Q + qg * 64;

    float sc[24];
    float m = -3.4e38f;
    for (int j = 0; j < L; ++j) {
        int ind = S - (S >> j);
        const float* kr = K + ((long long)bh * S + ind) * 64;
        float d = 0.f;
        for (int t = 0; t < 64; ++t) d += qr[t] * kr[t];
        d *= 0.125f;
        if (M[qg * (long long)S + ind]) d = -1e9f;
        sc[j] = d;
        m = fmaxf(m, d);
    }
    float sum = 0.f;
    for (int j = 0; j < L; ++j) { sc[j] = __expf(sc[j] - m); sum += sc[j]; }
    float inv = 1.0f / sum;

    float c[64];
    for (int t = 0; t < 64; ++t) c[t] = 0.f;
    for (int j = 0; j < L; ++j) {
        float a = sc[j] * inv;
        A[qg * L + j] = a;
        int ind = S - (S >> j);
        const float* vr = V + ((long long)bh * S + ind) * 64;
        for (int t = 0; t < 64; ++t) c[t] += a * vr[t];
    }
    for (int t = 0; t < 64; ++t) C[qg * 64 + t] = c[t];
}

// ---------------------------------------------------------------------------
extern "C" void kernel_launch(void* const* d_in, const int* in_sizes, int n_in,
                              void* d_out, int out_size)
{
    const float* Q = (const float*)d_in[0];
    const float* K = (const float*)d_in[1];
    const float* V = (const float*)d_in[2];
    const int*   M = (const int*)d_in[3];

    long long nq = (long long)in_sizes[0];      // B*H*S*64 (context elements)
    long long nm = (long long)in_sizes[3];      // B*H*S*S
    int S  = (int)((nm / nq) * 64);
    int BH = (int)(nq / ((long long)S * 64));

    int L = 0;
    while ((2 << L) <= S) ++L;                  // L = log2(S)
    if (L > 24) L = 24;

    long long nA = (long long)BH * S * L;
    float* C = (float*)d_out;
    // attn sits at the end of d_out (robust to harness padding)
    float* A = C + ((long long)out_size - nA);

    if (S == 4096) {
        dim3 grid(S / 128, BH);
        logtrans_fast<<<grid, 128>>>((const float4*)Q, (const float4*)K,
                                     (const float4*)V, M, (float4*)C, A);
    } else {
        long long BHS = (long long)BH * S;
        unsigned blocks = (unsigned)((BHS + 127) / 128);
        logtrans_generic<<<blocks, 128>>>(Q, K, V, M, C, A, S, L, BHS);
    }
}

// round 3
// speedup vs baseline: 1.0287x; 1.0287x over previous
#include <cuda_runtime.h>
#include <cstdint>

typedef unsigned long long u64;

__device__ __forceinline__ u64 pack2(float lo, float hi) {
    u64 r;
    asm("mov.b64 %0, {%1, %2};" : "=l"(r) : "f"(lo), "f"(hi));
    return r;
}
__device__ __forceinline__ void unpack2(u64 v, float& lo, float& hi) {
    asm("mov.b64 {%0, %1}, %2;" : "=f"(lo), "=f"(hi) : "l"(v));
}
__device__ __forceinline__ u64 fma2(u64 a, u64 b, u64 c) {
    u64 d;
    asm("fma.rn.f32x2 %0, %1, %2, %3;" : "=l"(d) : "l"(a), "l"(b), "l"(c));
    return d;
}

// ---------------------------------------------------------------------------
// Fast path: S=4096, D=64, L=12. One thread per q. K_g/V_g broadcast from
// SMEM; Q loads and context stores staged through per-warp SMEM transpose
// buffers so the gmem side is coalesced. Mask is int32 (harness materializes
// jnp.bool_ as int32).
// ---------------------------------------------------------------------------
__global__ __launch_bounds__(128)
void logtrans_fast(const float4* __restrict__ Q4,
                   const float4* __restrict__ K4,
                   const float4* __restrict__ V4,
                   const int* __restrict__ M,
                   float4* __restrict__ C4,
                   float* __restrict__ A)
{
    constexpr int S = 4096;
    constexpr int L = 12;

    __shared__ float4 ks[L][16];
    __shared__ float4 vs[L][16];
    __shared__ float4 buf[4][32][5];   // per-warp staging, padded row (5 float4)

    const int tid  = threadIdx.x;
    const int lane = tid & 31;
    const int w    = tid >> 5;
    const int bh   = blockIdx.y;
    const int q0   = blockIdx.x * 128;

    const int IND[L] = {0, 2048, 3072, 3584, 3840, 3968, 4032, 4064,
                        4080, 4088, 4092, 4094};

    // Fill K_g / V_g tiles (12 x 64 floats each)
    for (int e = tid; e < L * 16; e += 128) {
        int j = e >> 4, c = e & 15;
        long long row = (long long)bh * S + IND[j];
        ks[j][c] = __ldg(&K4[row * 16 + c]);
        vs[j][c] = __ldg(&V4[row * 16 + c]);
    }

    // Mask row for this q: 10 scalar int loads + one int4 covering 4092/4094
    const long long qg = (long long)bh * S + q0 + tid;
    const int* mrow = M + qg * (long long)S;
    unsigned mw = 0;
    {
        const int SI[10] = {0, 2048, 3072, 3584, 3840, 3968, 4032, 4064,
                            4080, 4088};
#pragma unroll
        for (int j = 0; j < 10; ++j)
            mw |= (mrow[SI[j]] ? 1u : 0u) << j;
        int4 t = *reinterpret_cast<const int4*>(mrow + 4092); // 4092..4095
        mw |= (t.x ? 1u : 0u) << 10;   // 4092
        mw |= (t.z ? 1u : 0u) << 11;   // 4094
    }
    __syncthreads();

    // ---------------- scores: s[j] = Q . K_g[j] ----------------
    u64 s2[L];
#pragma unroll
    for (int j = 0; j < L; ++j) s2[j] = 0ull;

    const float4* Qb = Q4 + ((long long)bh * S + q0 + w * 32) * 16;

#pragma unroll
    for (int dc = 0; dc < 4; ++dc) {
        __syncwarp();
        // coalesced gmem -> staged SMEM (this warp's 32 rows, 16-float chunk)
#pragma unroll
        for (int it = 0; it < 4; ++it) {
            int idx = it * 32 + lane;
            buf[w][idx >> 2][idx & 3] =
                Qb[(long long)(idx >> 2) * 16 + dc * 4 + (idx & 3)];
        }
        __syncwarp();
        ulonglong2 qv[4];
#pragma unroll
        for (int c = 0; c < 4; ++c)
            qv[c] = *reinterpret_cast<const ulonglong2*>(&buf[w][lane][c]);

#pragma unroll
        for (int j = 0; j < L; ++j) {
#pragma unroll
            for (int c = 0; c < 4; ++c) {
                ulonglong2 kv =
                    *reinterpret_cast<const ulonglong2*>(&ks[j][dc * 4 + c]);
                s2[j] = fma2(qv[c].x, kv.x, s2[j]);
                s2[j] = fma2(qv[c].y, kv.y, s2[j]);
            }
        }
    }

    // ---------------- mask + softmax ----------------
    float sc[L];
#pragma unroll
    for (int j = 0; j < L; ++j) {
        float lo, hi;
        unpack2(s2[j], lo, hi);
        float v = (lo + hi) * 0.125f;               // / sqrt(64)
        sc[j] = ((mw >> j) & 1u) ? -1e9f : v;
    }
    float m = sc[0];
#pragma unroll
    for (int j = 1; j < L; ++j) m = fmaxf(m, sc[j]);
    float sum = 0.f;
#pragma unroll
    for (int j = 0; j < L; ++j) {
        float e = __expf(sc[j] - m);
        sc[j] = e;
        sum += e;
    }
    float inv = 1.0f / sum;
    u64 a2[L];
#pragma unroll
    for (int j = 0; j < L; ++j) {
        float a = sc[j] * inv;
        sc[j] = a;
        a2[j] = pack2(a, a);
    }

    // ---------------- context = attn @ V_g ----------------
    float4* Cb = C4 + ((long long)bh * S + q0 + w * 32) * 16;

#pragma unroll
    for (int dc = 0; dc < 4; ++dc) {
        ulonglong2 acc[4];
#pragma unroll
        for (int c = 0; c < 4; ++c) { acc[c].x = 0ull; acc[c].y = 0ull; }
#pragma unroll
        for (int j = 0; j < L; ++j) {
#pragma unroll
            for (int c = 0; c < 4; ++c) {
                ulonglong2 vv =
                    *reinterpret_cast<const ulonglong2*>(&vs[j][dc * 4 + c]);
                acc[c].x = fma2(a2[j], vv.x, acc[c].x);
                acc[c].y = fma2(a2[j], vv.y, acc[c].y);
            }
        }
        __syncwarp();   // prior buf readers done
#pragma unroll
        for (int c = 0; c < 4; ++c)
            *reinterpret_cast<ulonglong2*>(&buf[w][lane][c]) = acc[c];
        __syncwarp();
        // staged SMEM -> coalesced gmem
#pragma unroll
        for (int it = 0; it < 4; ++it) {
            int idx = it * 32 + lane;
            Cb[(long long)(idx >> 2) * 16 + dc * 4 + (idx & 3)] =
                buf[w][idx >> 2][idx & 3];
        }
    }

    // ---------------- attn output (12 floats per q, 16B-aligned) ----------
    float* ap = A + qg * 12;
    float4 o0 = make_float4(sc[0], sc[1], sc[2],  sc[3]);
    float4 o1 = make_float4(sc[4], sc[5], sc[6],  sc[7]);
    float4 o2 = make_float4(sc[8], sc[9], sc[10], sc[11]);
    *reinterpret_cast<float4*>(ap)     = o0;
    *reinterpret_cast<float4*>(ap + 4) = o1;
    *reinterpret_cast<float4*>(ap + 8) = o2;
}

// ---------------------------------------------------------------------------
// Generic fallback (any power-of-two S, D=64)
// ---------------------------------------------------------------------------
__global__ void logtrans_generic(const float* __restrict__ Q,
                                 const float* __restrict__ K,
                                 const float* __restrict__ V,
                                 const int* __restrict__ M,
                                 float* __restrict__ C,
                                 float* __restrict__ A,
                                 int S, int L, long long BHS)
{
    long long qg = (long long)blockIdx.x * blockDim.x + threadIdx.x;
    if (qg >= BHS) return;
    int bh = (int)(qg / S);
    const float* qr = Q + qg * 64;

    float sc[24];
    float m = -3.4e38f;
    for (int j = 0; j < L; ++j) {
        int ind = S - (S >> j);
        const float* kr = K + ((long long)bh * S + ind) * 64;
        float d = 0.f;
        for (int t = 0; t < 64; ++t) d += qr[t] * kr[t];
        d *= 0.125f;
        if (M[qg * (long long)S + ind]) d = -1e9f;
        sc[j] = d;
        m = fmaxf(m, d);
    }
    float sum = 0.f;
    for (int j = 0; j < L; ++j) { sc[j] = __expf(sc[j] - m); sum += sc[j]; }
    float inv = 1.0f / sum;

    float c[64];
    for (int t = 0; t < 64; ++t) c[t] = 0.f;
    for (int j = 0; j < L; ++j) {
        float a = sc[j] * inv;
        A[qg * L + j] = a;
        int ind = S - (S >> j);
        const float* vr = V + ((long long)bh * S + ind) * 64;
        for (int t = 0; t < 64; ++t) c[t] += a * vr[t];
    }
    for (int t = 0; t < 64; ++t) C[qg * 64 + t] = c[t];
}

// ---------------------------------------------------------------------------
extern "C" void kernel_launch(void* const* d_in, const int* in_sizes, int n_in,
                              void* d_out, int out_size)
{
    const float* Q = (const float*)d_in[0];
    const float* K = (const float*)d_in[1];
    const float* V = (const float*)d_in[2];
    const int*   M = (const int*)d_in[3];

    long long nq = (long long)in_sizes[0];      // B*H*S*64 (context elements)
    long long nm = (long long)in_sizes[3];      // B*H*S*S
    int S  = (int)((nm / nq) * 64);
    int BH = (int)(nq / ((long long)S * 64));

    int L = 0;
    while ((2 << L) <= S) ++L;                  // L = log2(S)
    if (L > 24) L = 24;

    long long nA = (long long)BH * S * L;
    float* C = (float*)d_out;
    // attn sits at the end of d_out (robust to harness padding)
    float* A = C + ((long long)out_size - nA);

    if (S == 4096) {
        dim3 grid(S / 128, BH);
        logtrans_fast<<<grid, 128>>>((const float4*)Q, (const float4*)K,
                                     (const float4*)V, M, (float4*)C, A);
    } else {
        long long BHS = (long long)BH * S;
        unsigned blocks = (unsigned)((BHS + 127) / 128);
        logtrans_generic<<<blocks, 128>>>(Q, K, V, M, C, A, S, L, BHS);
    }
}

// round 4
// speedup vs baseline: 1.1242x; 1.0928x over previous
#include <cuda_runtime.h>
#include <cstdint>

typedef unsigned long long u64;

__device__ __forceinline__ u64 pack2(float lo, float hi) {
    u64 r;
    asm("mov.b64 %0, {%1, %2};" : "=l"(r) : "f"(lo), "f"(hi));
    return r;
}
__device__ __forceinline__ void unpack2(u64 v, float& lo, float& hi) {
    asm("mov.b64 {%0, %1}, %2;" : "=f"(lo), "=f"(hi) : "l"(v));
}
__device__ __forceinline__ u64 fma2(u64 a, u64 b, u64 c) {
    u64 d;
    asm("fma.rn.f32x2 %0, %1, %2, %3;" : "=l"(d) : "l"(a), "l"(b), "l"(c));
    return d;
}

// ---------------------------------------------------------------------------
// Fast path: S=4096, D=64, L=12.
// 4 threads per q-row (lane = 4*row + c). Thread c owns float4 columns
// {c, c+4, c+8, c+12} of its row -> 64B-contiguous per-row gmem access for
// both Q loads and context stores, no smem staging. All global loads issued
// up front; score reduction over the 4 lanes via butterfly shuffles.
// ---------------------------------------------------------------------------
__global__ __launch_bounds__(256, 4)
void logtrans_fast(const float4* __restrict__ Q4,
                   const float4* __restrict__ K4,
                   const float4* __restrict__ V4,
                   const int* __restrict__ M,
                   float4* __restrict__ C4,
                   float* __restrict__ A)
{
    constexpr int S = 4096;
    constexpr int L = 12;

    __shared__ float4 ks[L][16];
    __shared__ float4 vs[L][16];

    const int tid = threadIdx.x;
    const int c   = tid & 3;            // column-group within the row
    const int bh  = blockIdx.y;
    const int q0  = blockIdx.x * 64;    // 256 threads -> 64 rows per block

    const int IND[L] = {0, 2048, 3072, 3584, 3840, 3968, 4032, 4064,
                        4080, 4088, 4092, 4094};

    // ---- issue all global loads up front ----
    const long long qg = (long long)bh * S + q0 + (tid >> 2);
    const float4* Qb = Q4 + qg * 16;

    ulonglong2 qv[4];
#pragma unroll
    for (int i = 0; i < 4; ++i)
        qv[i] = *reinterpret_cast<const ulonglong2*>(&Qb[i * 4 + c]);

    const int* mrow = M + qg * (long long)S;
    unsigned mw = 0;
    mw |= (mrow[IND[c]]     ? 1u : 0u) << c;
    mw |= (mrow[IND[c + 4]] ? 1u : 0u) << (c + 4);
    mw |= (mrow[IND[c + 8]] ? 1u : 0u) << (c + 8);

    // ---- K/V gathered tiles (12 x 64 floats each) ----
    for (int e = tid; e < L * 16; e += 256) {
        int j = e >> 4, cc = e & 15;
        long long r = (long long)bh * S + IND[j];
        ks[j][cc] = __ldg(&K4[r * 16 + cc]);
        vs[j][cc] = __ldg(&V4[r * 16 + cc]);
    }
    __syncthreads();

    // ---- partial scores over this thread's 16 Q floats ----
    u64 s2[L];
#pragma unroll
    for (int j = 0; j < L; ++j) s2[j] = 0ull;

#pragma unroll
    for (int j = 0; j < L; ++j) {
#pragma unroll
        for (int i = 0; i < 4; ++i) {
            ulonglong2 kv =
                *reinterpret_cast<const ulonglong2*>(&ks[j][i * 4 + c]);
            s2[j] = fma2(qv[i].x, kv.x, s2[j]);
            s2[j] = fma2(qv[i].y, kv.y, s2[j]);
        }
    }

    float sc[L];
#pragma unroll
    for (int j = 0; j < L; ++j) {
        float lo, hi;
        unpack2(s2[j], lo, hi);
        sc[j] = lo + hi;
    }
    // reduce across the 4 lanes of this row (xor 1, xor 2 stay in-group)
#pragma unroll
    for (int j = 0; j < L; ++j) {
        sc[j] += __shfl_xor_sync(0xffffffffu, sc[j], 1);
        sc[j] += __shfl_xor_sync(0xffffffffu, sc[j], 2);
    }
    mw |= __shfl_xor_sync(0xffffffffu, mw, 1);
    mw |= __shfl_xor_sync(0xffffffffu, mw, 2);

    // ---- mask + softmax (redundant in the 4 lanes, cheap) ----
#pragma unroll
    for (int j = 0; j < L; ++j)
        sc[j] = ((mw >> j) & 1u) ? -1e9f : sc[j] * 0.125f;   // / sqrt(64)

    float m = sc[0];
#pragma unroll
    for (int j = 1; j < L; ++j) m = fmaxf(m, sc[j]);
    float sum = 0.f;
#pragma unroll
    for (int j = 0; j < L; ++j) {
        float e = __expf(sc[j] - m);
        sc[j] = e;
        sum += e;
    }
    float inv = 1.0f / sum;
#pragma unroll
    for (int j = 0; j < L; ++j) sc[j] *= inv;

    // ---- attn output: lanes 0..2 of the group write 16B each ----
    if (c < 3) {
        float4 o = make_float4(sc[c * 4], sc[c * 4 + 1],
                               sc[c * 4 + 2], sc[c * 4 + 3]);
        reinterpret_cast<float4*>(A + qg * 12)[c] = o;
    }

    // ---- context = attn @ V_g (two half-passes to bound registers) ----
    float4* Cb = C4 + qg * 16;
#pragma unroll
    for (int ih = 0; ih < 2; ++ih) {
        ulonglong2 acc[2];
        acc[0].x = acc[0].y = acc[1].x = acc[1].y = 0ull;
#pragma unroll
        for (int j = 0; j < L; ++j) {
            u64 aj = pack2(sc[j], sc[j]);
#pragma unroll
            for (int i2 = 0; i2 < 2; ++i2) {
                ulonglong2 vv = *reinterpret_cast<const ulonglong2*>(
                    &vs[j][(ih * 2 + i2) * 4 + c]);
                acc[i2].x = fma2(aj, vv.x, acc[i2].x);
                acc[i2].y = fma2(aj, vv.y, acc[i2].y);
            }
        }
#pragma unroll
        for (int i2 = 0; i2 < 2; ++i2)
            *reinterpret_cast<ulonglong2*>(&Cb[(ih * 2 + i2) * 4 + c]) =
                acc[i2];
    }
}

// ---------------------------------------------------------------------------
// Generic fallback (any power-of-two S, D=64)
// ---------------------------------------------------------------------------
__global__ void logtrans_generic(const float* __restrict__ Q,
                                 const float* __restrict__ K,
                                 const float* __restrict__ V,
                                 const int* __restrict__ M,
                                 float* __restrict__ C,
                                 float* __restrict__ A,
                                 int S, int L, long long BHS)
{
    long long qg = (long long)blockIdx.x * blockDim.x + threadIdx.x;
    if (qg >= BHS) return;
    int bh = (int)(qg / S);
    const float* qr = Q + qg * 64;

    float sc[24];
    float m = -3.4e38f;
    for (int j = 0; j < L; ++j) {
        int ind = S - (S >> j);
        const float* kr = K + ((long long)bh * S + ind) * 64;
        float d = 0.f;
        for (int t = 0; t < 64; ++t) d += qr[t] * kr[t];
        d *= 0.125f;
        if (M[qg * (long long)S + ind]) d = -1e9f;
        sc[j] = d;
        m = fmaxf(m, d);
    }
    float sum = 0.f;
    for (int j = 0; j < L; ++j) { sc[j] = __expf(sc[j] - m); sum += sc[j]; }
    float inv = 1.0f / sum;

    float cacc[64];
    for (int t = 0; t < 64; ++t) cacc[t] = 0.f;
    for (int j = 0; j < L; ++j) {
        float a = sc[j] * inv;
        A[qg * L + j] = a;
        int ind = S - (S >> j);
        const float* vr = V + ((long long)bh * S + ind) * 64;
        for (int t = 0; t < 64; ++t) cacc[t] += a * vr[t];
    }
    for (int t = 0; t < 64; ++t) C[qg * 64 + t] = cacc[t];
}

// ---------------------------------------------------------------------------
extern "C" void kernel_launch(void* const* d_in, const int* in_sizes, int n_in,
                              void* d_out, int out_size)
{
    const float* Q = (const float*)d_in[0];
    const float* K = (const float*)d_in[1];
    const float* V = (const float*)d_in[2];
    const int*   M = (const int*)d_in[3];

    long long nq = (long long)in_sizes[0];      // B*H*S*64 (context elements)
    long long nm = (long long)in_sizes[3];      // B*H*S*S
    int S  = (int)((nm / nq) * 64);
    int BH = (int)(nq / ((long long)S * 64));

    int L = 0;
    while ((2 << L) <= S) ++L;                  // L = log2(S)
    if (L > 24) L = 24;

    long long nA = (long long)BH * S * L;
    float* C = (float*)d_out;
    float* A = C + ((long long)out_size - nA);  // attn sits at end of d_out

    if (S == 4096) {
        dim3 grid(S / 64, BH);                  // 64 rows per 256-thread block
        logtrans_fast<<<grid, 256>>>((const float4*)Q, (const float4*)K,
                                     (const float4*)V, M, (float4*)C, A);
    } else {
        long long BHS = (long long)BH * S;
        unsigned blocks = (unsigned)((BHS + 127) / 128);
        logtrans_generic<<<blocks, 128>>>(Q, K, V, M, C, A, S, L, BHS);
    }
}